// round 12
// baseline (speedup 1.0000x reference)
#include <cuda_runtime.h>
#include <math.h>

// Problem constants
#define Vv 32000
#define Ee 512
#define Hh 512
#define G4 2048   // 4*H
#define Bb 64
#define Tt 256
#define GRID 128  // persistent CTAs, 1/SM -> all co-resident

typedef unsigned long long ull;

// ---------------- device scratch ----------------
// Activations use k-pair interleaved layout:
//   idx(k, b) = (k>>1)*128 + (b>>1)*4 + (k&1)*2 + (b&1)
// so a 16-byte block holds [k0b0, k0b1, k1b0, k1b1].
__device__ float g_WT_fc[(size_t)Ee * Vv];   // [k][v] transposed W_fc
__device__ float g_h[2][2][Hh * Bb];         // [ping][layer], interleaved layout
__device__ float g_x[Ee * Bb];               // interleaved layout
__device__ ull   g_amax[Bb];
__device__ unsigned g_bar_count;
__device__ volatile unsigned g_bar_gen;

// ---------------- packed f32x2 FMA helpers ----------------
__device__ __forceinline__ void ffma2(ull& d, ull a, ull b) {
    asm("fma.rn.f32x2 %0, %1, %2, %0;" : "+l"(d) : "l"(a), "l"(b));
}
__device__ __forceinline__ ull pack2(float v) {
    ull r; asm("mov.b64 %0, {%1, %1};" : "=l"(r) : "f"(v)); return r;
}
__device__ __forceinline__ float2 unpack2(ull a) {
    float2 r; asm("mov.b64 {%0, %1}, %2;" : "=f"(r.x), "=f"(r.y) : "l"(a)); return r;
}
__device__ __forceinline__ ull amax_pack(float f, int idx) {
    unsigned b = __float_as_uint(f);
    unsigned key = (b & 0x80000000u) ? ~b : (b | 0x80000000u);
    return ((ull)key << 32) | (ull)(0xFFFFFFFFu - (unsigned)idx);
}

// ---------------- grid-wide barrier ----------------
__device__ __forceinline__ void gsync() {
    __threadfence();
    __syncthreads();
    if (threadIdx.x == 0) {
        unsigned gen = g_bar_gen;
        unsigned t = atomicAdd(&g_bar_count, 1u);
        if (t == GRID - 1) {
            g_bar_count = 0;
            __threadfence();
            g_bar_gen = gen + 1;
        } else {
            while (g_bar_gen == gen) { }
        }
    }
    __syncthreads();
}

// ---------------- gates matmul: 512 k, 16-deep k-pair prefetch ----------------
// actq = act_base + (b>>1)*4 ; each float4 at +kk*128 holds this b-pair's 2 k's.
// bodd selects (y,w) vs (x,z).  Weights: smem wq[k] = 16B (4 gates), broadcast.
__device__ __forceinline__ void mmgates(ull& acc01, ull& acc23,
                                        unsigned wofs, const float* actq, int bodd) {
    extern __shared__ float wsm[];
    const ulonglong2* wq = (const ulonglong2*)(wsm + wofs);
    float4 a0[16], a1[16];
    #pragma unroll
    for (int i = 0; i < 16; i++) a0[i] = __ldcg((const float4*)(actq + i * 128));
    int kk = 0;
    #pragma unroll 1
    for (int c = 0; c < 8; c++) {            // 8 x 32 kk = 256 kk = 512 k
        #pragma unroll
        for (int i = 0; i < 16; i++)
            a1[i] = __ldcg((const float4*)(actq + (kk + 16 + i) * 128));
        #pragma unroll
        for (int i = 0; i < 16; i++) {
            int k2 = (kk + i) * 2;
            ulonglong2 w0 = wq[k2], w1 = wq[k2 + 1];
            float e0 = bodd ? a0[i].y : a0[i].x;
            float e1 = bodd ? a0[i].w : a0[i].z;
            ull p0 = pack2(e0), p1 = pack2(e1);
            ffma2(acc01, w0.x, p0); ffma2(acc23, w0.y, p0);
            ffma2(acc01, w1.x, p1); ffma2(acc23, w1.y, p1);
        }
        int ka = (c < 7) ? kk + 32 : 0;
        #pragma unroll
        for (int i = 0; i < 16; i++)
            a0[i] = __ldcg((const float4*)(actq + (ka + i) * 128));
        #pragma unroll
        for (int i = 0; i < 16; i++) {
            int k2 = (kk + 16 + i) * 2;
            ulonglong2 w0 = wq[k2], w1 = wq[k2 + 1];
            float e0 = bodd ? a1[i].y : a1[i].x;
            float e1 = bodd ? a1[i].w : a1[i].z;
            ull p0 = pack2(e0), p1 = pack2(e1);
            ffma2(acc01, w0.x, p0); ffma2(acc23, w0.y, p0);
            ffma2(acc01, w1.x, p1); ffma2(acc23, w1.y, p1);
        }
        kk += 32;
    }
}

// ---------------- LSTM layer ----------------
// thread = (u = tid>>6, b = tid&63); CTA owns units cta*4 .. +3, all gates.
__device__ __forceinline__ void lstm_layer(
    unsigned lrow,
    const float* __restrict__ inp, const float* __restrict__ hin,
    float* __restrict__ hout, float& creg,
    const float* __restrict__ bih, const float* __restrict__ bhh,
    int cta, int tid)
{
    int u = tid >> 6, b = tid & 63;
    int bodd = b & 1;
    const float* inq = inp + (b >> 1) * 4;
    const float* hq  = hin + (b >> 1) * 4;
    ull acc01 = 0ull, acc23 = 0ull;
    mmgates(acc01, acc23, (lrow + u) * 2048u,     inq, bodd);   // W_ih
    mmgates(acc01, acc23, (lrow + 4 + u) * 2048u, hq,  bodd);   // W_hh
    int j0 = cta * 4 + u;
    float2 a01 = unpack2(acc01), a23 = unpack2(acc23);
    float iv = a01.x + bih[j0]        + bhh[j0];
    float fv = a01.y + bih[512 + j0]  + bhh[512 + j0];
    float gv = a23.x + bih[1024 + j0] + bhh[1024 + j0];
    float ov = a23.y + bih[1536 + j0] + bhh[1536 + j0];
    float ig = 1.0f / (1.0f + expf(-iv));
    float fg = 1.0f / (1.0f + expf(-fv));
    float og = 1.0f / (1.0f + expf(-ov));
    float cn = fg * creg + ig * tanhf(gv);
    float hn = og * tanhf(cn);
    creg = cn;
    // interleaved store: k index = j0
    int off = (j0 >> 1) * 128 + (b >> 1) * 4 + (j0 & 1) * 2 + (b & 1);
    __stcg(&hout[off], hn);
}

// ---------------- single persistent kernel ----------------
// dynamic smem: [0,32768) gate weights; [32768, 32768+2*4224) FC stage buffers
#define FSM_OFF 32768
#define FSTRIDE 132     // 16k*8v + 4 pad floats per vg row

__global__ void __launch_bounds__(256, 1)
kmain(const int* __restrict__ x, const float* __restrict__ emb,
      const float* __restrict__ W_ih, const float* __restrict__ W_hh,
      const float* __restrict__ b_ih, const float* __restrict__ b_hh,
      const float* __restrict__ W_fc, const float* __restrict__ bfc,
      float* __restrict__ out)
{
    extern __shared__ float wsm[];
    __shared__ int s_tok;

    int tid = threadIdx.x;
    int cta = blockIdx.x;

    // ================= per-replay init =================
    ((float2*)&g_h[0][0][0])[cta * 256 + tid] = make_float2(0.0f, 0.0f);
    if (cta < Bb) {                          // x0 = embedding[x[:,0]]
        int tok = x[cta * Tt];
        float2 e2 = ((const float2*)(emb + (size_t)tok * Ee))[tid];
        int base = tid * 128 + (cta >> 1) * 4 + (cta & 1);
        g_x[base]     = e2.x;
        g_x[base + 2] = e2.y;
    }
    // gate weights -> smem, [row][k][gate]; row = l*8 + m*4 + u
    #pragma unroll 1
    for (int r = 0; r < 16; r++) {
        int l = r >> 3, m = (r >> 2) & 1, u = r & 3;
        const float* base = (m ? W_hh : W_ih) + (size_t)l * G4 * 512;
        #pragma unroll
        for (int q = 0; q < 4; q++) {
            const float* src = base + (size_t)(q * 512 + cta * 4 + u) * 512;
            float2 v = *(const float2*)(src + tid * 2);
            wsm[r * 2048 + (tid * 2) * 4 + q]     = v.x;
            wsm[r * 2048 + (tid * 2 + 1) * 4 + q] = v.y;
        }
    }
    // transpose W_fc -> g_WT_fc [k][v]
    if (tid < 250) {
        int v = cta * 250 + tid;
        const float4* src = (const float4*)(W_fc + (size_t)v * Ee);
        #pragma unroll 4
        for (int kq = 0; kq < 128; kq++) {
            float4 r = src[kq];
            size_t k = (size_t)kq * 4;
            g_WT_fc[k * Vv + v]       = r.x;
            g_WT_fc[(k + 1) * Vv + v] = r.y;
            g_WT_fc[(k + 2) * Vv + v] = r.z;
            g_WT_fc[(k + 3) * Vv + v] = r.w;
        }
    }
    if (tid < Bb && cta == 0) g_amax[tid] = 0ull;

    float creg0 = 0.0f, creg1 = 0.0f;
    gsync();

    // ================= timestep loop =================
    for (int t = 0; t < Tt; t++) {
        int pi = t & 1, po = pi ^ 1;

        lstm_layer(0, g_x, &g_h[pi][0][0], &g_h[po][0][0], creg0,
                   b_ih, b_hh, cta, tid);
        gsync();

        lstm_layer(8, &g_h[po][0][0], &g_h[pi][1][0], &g_h[po][1][0], creg1,
                   b_ih + G4, b_hh + G4, cta, tid);
        gsync();

        // ---- FC head: warp = batch-octet bq, lane = vocab-group vg (8 v) ----
        if (cta < 125) {
            int bq = tid >> 5, vg = tid & 31;
            int v0 = cta * 256 + vg * 8;
            const float* hb = (const float*)&g_h[po][1][0] + bq * 16;
            const float* WTc = g_WT_fc + cta * 256;
            float* fsm = wsm + FSM_OFF;

            ull acc[8][4];
            #pragma unroll
            for (int v = 0; v < 8; v++) {
                acc[v][0] = 0; acc[v][1] = 0; acc[v][2] = 0; acc[v][3] = 0;
            }

#define FCSTAGE(dst, cc) { \
    _Pragma("unroll") \
    for (int s = 0; s < 2; s++) { \
        int slot = tid + s * 256; \
        int svg = slot & 31, skr = slot >> 5; \
        const float4* src = (const float4*)(WTc + (size_t)((cc) * 16 + skr) * Vv + svg * 8); \
        float4 x0 = src[0], x1 = src[1]; \
        *(float4*)((dst) + svg * FSTRIDE + skr * 8)     = x0; \
        *(float4*)((dst) + svg * FSTRIDE + skr * 8 + 4) = x1; } }

#define FCALOAD(A, kk) { \
    const ulonglong2* ar = (const ulonglong2*)(hb + (size_t)(kk) * 128); \
    A[0] = __ldcg(ar); A[1] = __ldcg(ar + 1); \
    A[2] = __ldcg(ar + 2); A[3] = __ldcg(ar + 3); }

#define FCCOMP(A, wcb, i) { \
    const float* w0 = (wcb) + (2 * (i)) * 8; \
    const float* w1 = (wcb) + (2 * (i) + 1) * 8; \
    float4 w0a = *(const float4*)w0, w0b = *(const float4*)(w0 + 4); \
    float4 w1a = *(const float4*)w1, w1b = *(const float4*)(w1 + 4); \
    float wf0[8] = {w0a.x, w0a.y, w0a.z, w0a.w, w0b.x, w0b.y, w0b.z, w0b.w}; \
    float wf1[8] = {w1a.x, w1a.y, w1a.z, w1a.w, w1b.x, w1b.y, w1b.z, w1b.w}; \
    _Pragma("unroll") \
    for (int v = 0; v < 8; v++) { \
        ull wp = pack2(wf0[v]); \
        ffma2(acc[v][0], A[0].x, wp); ffma2(acc[v][1], A[1].x, wp); \
        ffma2(acc[v][2], A[2].x, wp); ffma2(acc[v][3], A[3].x, wp); } \
    _Pragma("unroll") \
    for (int v = 0; v < 8; v++) { \
        ull wp = pack2(wf1[v]); \
        ffma2(acc[v][0], A[0].y, wp); ffma2(acc[v][1], A[1].y, wp); \
        ffma2(acc[v][2], A[2].y, wp); ffma2(acc[v][3], A[3].y, wp); } }

            FCSTAGE(fsm, 0);
            ulonglong2 aA[4], aB[4];
            FCALOAD(aA, 0);
            __syncthreads();

            #pragma unroll 1
            for (int c = 0; c < 32; c++) {           // 32 chunks x 16 k
                if (c < 31) { float* dst = fsm + ((c + 1) & 1) * (32 * FSTRIDE);
                              FCSTAGE(dst, c + 1); }
                const float* wcb = fsm + (c & 1) * (32 * FSTRIDE) + vg * FSTRIDE;
                #pragma unroll
                for (int i = 0; i < 8; i += 2) {
                    int kkg = c * 8 + i;
                    FCALOAD(aB, kkg + 1);
                    FCCOMP(aA, wcb, i);
                    int kn = (kkg + 2 < 256) ? kkg + 2 : 0;
                    FCALOAD(aA, kn);
                    FCCOMP(aB, wcb, i + 1);
                }
                __syncthreads();
            }
#undef FCSTAGE
#undef FCALOAD
#undef FCCOMP

            float bias[8];
            {
                float4 b0 = *(const float4*)(bfc + v0);
                float4 b1 = *(const float4*)(bfc + v0 + 4);
                bias[0] = b0.x; bias[1] = b0.y; bias[2] = b0.z; bias[3] = b0.w;
                bias[4] = b1.x; bias[5] = b1.y; bias[6] = b1.z; bias[7] = b1.w;
            }
            #pragma unroll
            for (int bb = 0; bb < 8; bb++) {
                int b = bq * 8 + bb;
                float vals[8];
                #pragma unroll
                for (int v = 0; v < 8; v++) {
                    float2 t2 = unpack2(acc[v][bb >> 1]);
                    vals[v] = ((bb & 1) ? t2.y : t2.x) + bias[v];
                }
                if (t == Tt - 1) {
                    *(float4*)(out + (size_t)b * Vv + v0) =
                        make_float4(vals[0], vals[1], vals[2], vals[3]);
                    *(float4*)(out + (size_t)b * Vv + v0 + 4) =
                        make_float4(vals[4], vals[5], vals[6], vals[7]);
                } else {
                    float mv = vals[0]; int mi = v0;
                    #pragma unroll
                    for (int v = 1; v < 8; v++)
                        if (vals[v] > mv) { mv = vals[v]; mi = v0 + v; }
                    #pragma unroll
                    for (int o = 16; o > 0; o >>= 1) {
                        float ovv = __shfl_down_sync(0xffffffffu, mv, o);
                        int   oii = __shfl_down_sync(0xffffffffu, mi, o);
                        if (ovv > mv || (ovv == mv && oii < mi)) { mv = ovv; mi = oii; }
                    }
                    if (vg == 0) atomicMax(&g_amax[b], amax_pack(mv, mi));
                }
            }
        }
        gsync();

        // ---- pick token, gather next embedding into g_x ----
        if (t < Tt - 1 && cta < Bb) {
            if (tid == 0) {
                ull pv = __ldcg((const ull*)&g_amax[cta]);
                s_tok = (int)(0xFFFFFFFFu - (unsigned)(pv & 0xFFFFFFFFull));
                atomicExch(&g_amax[cta], 0ull);
            }
            __syncthreads();
            int tok = s_tok;
            float2 e2 = *(const float2*)(emb + (size_t)tok * Ee + tid * 2);
            int base = tid * 128 + (cta >> 1) * 4 + (cta & 1);
            __stcg(&g_x[base],     e2.x);
            __stcg(&g_x[base + 2], e2.y);
        }
        gsync();
    }
}

// ---------------- host driver ----------------
extern "C" void kernel_launch(void* const* d_in, const int* in_sizes, int n_in,
                              void* d_out, int out_size) {
    const int*   x    = (const int*)d_in[0];
    const float* emb  = (const float*)d_in[1];
    const float* W_ih = (const float*)d_in[2];
    const float* W_hh = (const float*)d_in[3];
    const float* b_ih = (const float*)d_in[4];
    const float* b_hh = (const float*)d_in[5];
    const float* W_fc = (const float*)d_in[6];
    const float* b_fc = (const float*)d_in[7];
    float* out = (float*)d_out;

    const int SMEM = (32768 + 2 * 32 * FSTRIDE) * (int)sizeof(float); // 128K + 33K
    cudaFuncSetAttribute(kmain, cudaFuncAttributeMaxDynamicSharedMemorySize, SMEM);

    kmain<<<GRID, 256, SMEM>>>(x, emb, W_ih, W_hh, b_ih, b_hh, W_fc, b_fc, out);
}